// round 5
// baseline (speedup 1.0000x reference)
#include <cuda_runtime.h>

#define DIMD  1024
#define NH    16
#define DH    64
#define BATCH 4
#define SEQ   2048
#define MTOT  (BATCH*SEQ)   // 8192

// Scratch (allocation-free rule: __device__ globals)
__device__ float g_Q[BATCH*NH*SEQ*DH];   // [B,H,S,Dh]
__device__ float g_K[BATCH*NH*SEQ*DH];
__device__ float g_V[BATCH*NH*SEQ*DH];
__device__ float g_A[MTOT*DIMD];         // attention output, [B,S,D]

__device__ __forceinline__ float f2tf32(float x) {
    unsigned u;
    asm("cvt.rna.tf32.f32 %0, %1;" : "=r"(u) : "f"(x));
    return __uint_as_float(u);
}
__device__ __forceinline__ unsigned tf32u(float x) {
    unsigned u;
    asm("cvt.rna.tf32.f32 %0, %1;" : "=r"(u) : "f"(x));
    return u;
}

__device__ __forceinline__ void mma_tf32(
    float& c0, float& c1, float& c2, float& c3,
    unsigned a0, unsigned a1, unsigned a2, unsigned a3,
    unsigned b0, unsigned b1)
{
    asm volatile(
        "mma.sync.aligned.m16n8k8.row.col.f32.tf32.tf32.f32 "
        "{%0,%1,%2,%3}, {%4,%5,%6,%7}, {%8,%9}, {%0,%1,%2,%3};"
        : "+f"(c0), "+f"(c1), "+f"(c2), "+f"(c3)
        : "r"(a0), "r"(a1), "r"(a2), "r"(a3), "r"(b0), "r"(b1));
}

__device__ __forceinline__ void cp16(float* dst, const float* src) {
    unsigned s = (unsigned)__cvta_generic_to_shared(dst);
    asm volatile("cp.async.cg.shared.global [%0], [%1], 16;\n" :: "r"(s), "l"(src));
}
__device__ __forceinline__ void cp_commit() {
    asm volatile("cp.async.commit_group;\n");
}
template<int N>
__device__ __forceinline__ void cp_wait() {
    asm volatile("cp.async.wait_group %0;\n" :: "n"(N));
}

// ---------------------------------------------------------------------------
// TF32 GEMM: block 128x128, 4 warps (2x2), warp tile 64x64.
// 4-stage cp.async pipeline, BK=16. cvt.rna applied after fragment LDS.
// A smem stride 20 (banks 20*qr+qc distinct), B stride 136 (8*qc+qr distinct).
// ---------------------------------------------------------------------------
#define STAGES   4
#define BK       16
#define AS_ST    20
#define BS_ST    136
#define AS_STAGE (128*AS_ST)   // 2560
#define BS_STAGE (16*BS_ST)    // 2176
#define GEMM_SMEM_FLOATS (STAGES*(AS_STAGE+BS_STAGE))   // 18944
#define GEMM_SMEM_BYTES  (GEMM_SMEM_FLOATS*4)           // 75776

template<int MODE>
__global__ __launch_bounds__(128, 2)
void gemm_tf32(const float* __restrict__ A, const float* __restrict__ B,
               const float* __restrict__ bias, float* __restrict__ out, int N)
{
    extern __shared__ float smg[];
    float* Asm = smg;                       // [STAGES][128][20]
    float* Bsm = smg + STAGES*AS_STAGE;     // [STAGES][16][136]

    const int tid  = threadIdx.x;
    const int lane = tid & 31;
    const int warp = tid >> 5;
    const int warp_m = warp & 1;            // 0..1 -> 64-row strip
    const int warp_n = warp >> 1;           // 0..1 -> 64-col strip
    const int qr = lane >> 2;               // 0..7
    const int qc = lane & 3;                // 0..3

    const int rowStart = blockIdx.y * 128;
    const int colStart = blockIdx.x * 128;
    const float* Ap = (MODE == 0) ? A : g_A;

    float acc[4][8][4];
    #pragma unroll
    for (int i = 0; i < 4; i++)
        #pragma unroll
        for (int j = 0; j < 8; j++)
            #pragma unroll
            for (int c = 0; c < 4; c++) acc[i][j][c] = 0.f;

    auto load_stage = [&](int s, int k0) {
        float* as = Asm + s*AS_STAGE;
        float* bs = Bsm + s*BS_STAGE;
        #pragma unroll
        for (int i = 0; i < 4; i++) {
            // A: thread = row, 4 quads along k
            cp16(as + tid*AS_ST + i*4,
                 Ap + (long)(rowStart + tid)*DIMD + k0 + i*4);
            // B: 16 rows x 32 col-quads
            const int q = tid + i*128;
            cp16(bs + (q >> 5)*BS_ST + (q & 31)*4,
                 B + (long)(k0 + (q >> 5))*N + colStart + (q & 31)*4);
        }
    };

    #pragma unroll
    for (int s = 0; s < STAGES-1; s++) { load_stage(s, s*BK); cp_commit(); }
    cp_wait<STAGES-2>();
    __syncthreads();

    const int NITER = DIMD / BK;   // 64
    for (int it = 0; it < NITER; it++) {
        const int cur = it & (STAGES-1);
        const int nk = it + STAGES - 1;
        if (nk < NITER) load_stage(nk & (STAGES-1), nk*BK);
        cp_commit();

        const float* as = Asm + cur*AS_STAGE;
        const float* bs = Bsm + cur*BS_STAGE;
        #pragma unroll
        for (int ks = 0; ks < 2; ks++) {
            const int kb = ks*8;
            unsigned a[4][4], b[8][2];
            #pragma unroll
            for (int ma = 0; ma < 4; ma++) {
                const int r = warp_m*64 + ma*16 + qr;
                a[ma][0] = tf32u(as[(r    )*AS_ST + kb + qc    ]);
                a[ma][1] = tf32u(as[(r + 8)*AS_ST + kb + qc    ]);
                a[ma][2] = tf32u(as[(r    )*AS_ST + kb + qc + 4]);
                a[ma][3] = tf32u(as[(r + 8)*AS_ST + kb + qc + 4]);
            }
            #pragma unroll
            for (int nb = 0; nb < 8; nb++) {
                const int cc = warp_n*64 + nb*8 + qr;
                b[nb][0] = tf32u(bs[(kb + qc    )*BS_ST + cc]);
                b[nb][1] = tf32u(bs[(kb + qc + 4)*BS_ST + cc]);
            }
            #pragma unroll
            for (int ma = 0; ma < 4; ma++)
                #pragma unroll
                for (int nb = 0; nb < 8; nb++)
                    mma_tf32(acc[ma][nb][0], acc[ma][nb][1],
                             acc[ma][nb][2], acc[ma][nb][3],
                             a[ma][0], a[ma][1], a[ma][2], a[ma][3],
                             b[nb][0], b[nb][1]);
        }
        cp_wait<STAGES-2>();
        __syncthreads();
    }

    #pragma unroll
    for (int ma = 0; ma < 4; ma++) {
        const int row0 = rowStart + warp_m*64 + ma*16 + qr;
        #pragma unroll
        for (int nb = 0; nb < 8; nb++) {
            const int col = colStart + warp_n*64 + nb*8 + qc*2;
            const float b0 = bias[col], b1 = bias[col + 1];
            float2 v0 = make_float2(acc[ma][nb][0] + b0, acc[ma][nb][1] + b1);
            float2 v1 = make_float2(acc[ma][nb][2] + b0, acc[ma][nb][3] + b1);
            if (MODE == 0) {
                const int part = col >> 10;
                const int dcol = col & 1023;
                const int head = dcol >> 6;
                const int dh   = dcol & 63;
                float* dst = (part == 0) ? g_Q : (part == 1) ? g_K : g_V;
                {
                    const int bb = row0 >> 11, s = row0 & 2047;
                    *(float2*)(dst + (((bb*NH + head)*SEQ + s) << 6) + dh) = v0;
                }
                {
                    const int row1 = row0 + 8;
                    const int bb = row1 >> 11, s = row1 & 2047;
                    *(float2*)(dst + (((bb*NH + head)*SEQ + s) << 6) + dh) = v1;
                }
            } else {
                *(float2*)(out + (long)row0*N + col) = v0;
                *(float2*)(out + (long)(row0 + 8)*N + col) = v1;
            }
        }
    }
}

// ---------------------------------------------------------------------------
// TF32 tensor-core flash attention (exact round-3 version, the 932us one).
// ---------------------------------------------------------------------------
#define QS_OFF 0
#define KS_OFF 8704               // 128*68
#define VT_OFF 13056              // + 64*68
#define PS_OFF 17408              // + 64*68
#define ATTN_SMEM_FLOATS 26112    // + 128*68
#define ATTN_SMEM_BYTES (ATTN_SMEM_FLOATS*4)   // 104448

__global__ __launch_bounds__(256, 2)
void attn_tf32()
{
    extern __shared__ float sm[];
    float* Qs = sm + QS_OFF;   // [128][68]
    float* Ks = sm + KS_OFF;   // [64][68]
    float* Vt = sm + VT_OFF;   // [64][68]  (transposed V)
    float* Ps = sm + PS_OFF;   // [128][68]

    const int tid  = threadIdx.x;
    const int lane = tid & 31;
    const int warp = tid >> 5;
    const int qr = lane >> 2;
    const int qc = lane & 3;

    const int qt = (int)(gridDim.x - 1) - (int)blockIdx.x;
    const int h = blockIdx.y, b = blockIdx.z;
    const int q0 = qt << 7;

    const long hb = (long)(b*NH + h) * SEQ * DH;
    const float* Qg = g_Q + hb;
    const float* Kg = g_K + hb;
    const float* Vg = g_V + hb;

    #pragma unroll
    for (int i = 0; i < 8; i++) {
        const int q = tid + i*256;
        const int r = q >> 4, dq = (q & 15) << 2;
        float4 t = *(const float4*)(Qg + (q0 + r)*DH + dq);
        float4 c;
        c.x = f2tf32(t.x * 0.125f); c.y = f2tf32(t.y * 0.125f);
        c.z = f2tf32(t.z * 0.125f); c.w = f2tf32(t.w * 0.125f);
        *(float4*)(Qs + r*68 + dq) = c;
    }

    float m0 = -1e30f, m1 = -1e30f, l0 = 0.f, l1 = 0.f;
    float o[8][4];
    #pragma unroll
    for (int nb = 0; nb < 8; nb++)
        #pragma unroll
        for (int c = 0; c < 4; c++) o[nb][c] = 0.f;

    const int rowA = warp*16 + qr;
    const int ktiles = 2*qt + 2;

    for (int kt = 0; kt < ktiles; kt++) {
        const int k0 = kt << 6;
        __syncthreads();

        #pragma unroll
        for (int i = 0; i < 4; i++) {
            const int q = tid + i*256;
            const int r = q >> 4, dq = (q & 15) << 2;
            float4 t = *(const float4*)(Kg + (k0 + r)*DH + dq);
            float4 c;
            c.x = f2tf32(t.x); c.y = f2tf32(t.y);
            c.z = f2tf32(t.z); c.w = f2tf32(t.w);
            *(float4*)(Ks + r*68 + dq) = c;
        }
        {
            const int key = tid & 63;
            const int dq0 = (tid >> 6) << 2;
            #pragma unroll
            for (int i = 0; i < 4; i++) {
                const int dq = dq0 + i*16;
                float4 t = *(const float4*)(Vg + (k0 + key)*DH + dq);
                Vt[(dq+0)*68 + key] = f2tf32(t.x);
                Vt[(dq+1)*68 + key] = f2tf32(t.y);
                Vt[(dq+2)*68 + key] = f2tf32(t.z);
                Vt[(dq+3)*68 + key] = f2tf32(t.w);
            }
        }
        __syncthreads();

        float sv[8][4];
        #pragma unroll
        for (int nb = 0; nb < 8; nb++)
            #pragma unroll
            for (int c = 0; c < 4; c++) sv[nb][c] = 0.f;

        #pragma unroll
        for (int ks = 0; ks < 8; ks++) {
            const int kb = ks*8;
            const unsigned a0 = __float_as_uint(Qs[(rowA    )*68 + kb+qc  ]);
            const unsigned a1 = __float_as_uint(Qs[(rowA + 8)*68 + kb+qc  ]);
            const unsigned a2 = __float_as_uint(Qs[(rowA    )*68 + kb+qc+4]);
            const unsigned a3 = __float_as_uint(Qs[(rowA + 8)*68 + kb+qc+4]);
            #pragma unroll
            for (int nb = 0; nb < 8; nb++) {
                const unsigned b0 = __float_as_uint(Ks[(nb*8+qr)*68 + kb+qc  ]);
                const unsigned b1 = __float_as_uint(Ks[(nb*8+qr)*68 + kb+qc+4]);
                mma_tf32(sv[nb][0], sv[nb][1], sv[nb][2], sv[nb][3],
                         a0, a1, a2, a3, b0, b1);
            }
        }

        if (kt >= 2*qt) {
            const int qg0 = q0 + rowA;
            #pragma unroll
            for (int nb = 0; nb < 8; nb++) {
                const int kg = k0 + nb*8 + 2*qc;
                if (kg     > qg0    ) sv[nb][0] = -1e30f;
                if (kg + 1 > qg0    ) sv[nb][1] = -1e30f;
                if (kg     > qg0 + 8) sv[nb][2] = -1e30f;
                if (kg + 1 > qg0 + 8) sv[nb][3] = -1e30f;
            }
        }

        float mx0 = -1e30f, mx1 = -1e30f;
        #pragma unroll
        for (int nb = 0; nb < 8; nb++) {
            mx0 = fmaxf(mx0, fmaxf(sv[nb][0], sv[nb][1]));
            mx1 = fmaxf(mx1, fmaxf(sv[nb][2], sv[nb][3]));
        }
        mx0 = fmaxf(mx0, __shfl_xor_sync(0xffffffffu, mx0, 1));
        mx0 = fmaxf(mx0, __shfl_xor_sync(0xffffffffu, mx0, 2));
        mx1 = fmaxf(mx1, __shfl_xor_sync(0xffffffffu, mx1, 1));
        mx1 = fmaxf(mx1, __shfl_xor_sync(0xffffffffu, mx1, 2));

        const float m0n = fmaxf(m0, mx0);
        const float m1n = fmaxf(m1, mx1);
        const float al0 = __expf(m0 - m0n);
        const float al1 = __expf(m1 - m1n);
        m0 = m0n; m1 = m1n;

        float ps0 = 0.f, ps1 = 0.f;
        #pragma unroll
        for (int nb = 0; nb < 8; nb++) {
            sv[nb][0] = __expf(sv[nb][0] - m0n);
            sv[nb][1] = __expf(sv[nb][1] - m0n);
            sv[nb][2] = __expf(sv[nb][2] - m1n);
            sv[nb][3] = __expf(sv[nb][3] - m1n);
            ps0 += sv[nb][0] + sv[nb][1];
            ps1 += sv[nb][2] + sv[nb][3];
        }
        ps0 += __shfl_xor_sync(0xffffffffu, ps0, 1);
        ps0 += __shfl_xor_sync(0xffffffffu, ps0, 2);
        ps1 += __shfl_xor_sync(0xffffffffu, ps1, 1);
        ps1 += __shfl_xor_sync(0xffffffffu, ps1, 2);
        l0 = l0*al0 + ps0;
        l1 = l1*al1 + ps1;
        #pragma unroll
        for (int nb = 0; nb < 8; nb++) {
            o[nb][0] *= al0; o[nb][1] *= al0;
            o[nb][2] *= al1; o[nb][3] *= al1;
        }

        #pragma unroll
        for (int nb = 0; nb < 8; nb++) {
            const int kc = nb*8 + 2*qc;
            *(float2*)(Ps + (rowA    )*68 + kc) =
                make_float2(f2tf32(sv[nb][0]), f2tf32(sv[nb][1]));
            *(float2*)(Ps + (rowA + 8)*68 + kc) =
                make_float2(f2tf32(sv[nb][2]), f2tf32(sv[nb][3]));
        }
        __syncthreads();

        #pragma unroll
        for (int ks = 0; ks < 8; ks++) {
            const int kb = ks*8;
            const unsigned a0 = __float_as_uint(Ps[(rowA    )*68 + kb+qc  ]);
            const unsigned a1 = __float_as_uint(Ps[(rowA + 8)*68 + kb+qc  ]);
            const unsigned a2 = __float_as_uint(Ps[(rowA    )*68 + kb+qc+4]);
            const unsigned a3 = __float_as_uint(Ps[(rowA + 8)*68 + kb+qc+4]);
            #pragma unroll
            for (int nb = 0; nb < 8; nb++) {
                const unsigned b0 = __float_as_uint(Vt[(nb*8+qr)*68 + kb+qc  ]);
                const unsigned b1 = __float_as_uint(Vt[(nb*8+qr)*68 + kb+qc+4]);
                mma_tf32(o[nb][0], o[nb][1], o[nb][2], o[nb][3],
                         a0, a1, a2, a3, b0, b1);
            }
        }
    }

    const float inv0 = 1.0f / l0;
    const float inv1 = 1.0f / l1;
    const long r0 = (long)(b*SEQ + q0 + rowA);
    #pragma unroll
    for (int nb = 0; nb < 8; nb++) {
        const int col = h*DH + nb*8 + 2*qc;
        *(float2*)(g_A + r0*DIMD + col) =
            make_float2(o[nb][0]*inv0, o[nb][1]*inv0);
        *(float2*)(g_A + (r0 + 8)*DIMD + col) =
            make_float2(o[nb][2]*inv1, o[nb][3]*inv1);
    }
}

// ---------------------------------------------------------------------------
extern "C" void kernel_launch(void* const* d_in, const int* in_sizes, int n_in,
                              void* d_out, int out_size)
{
    const float* x      = (const float*)d_in[0];
    const float* w_qkv  = (const float*)d_in[1];
    const float* b_qkv  = (const float*)d_in[2];
    const float* w_proj = (const float*)d_in[3];
    const float* b_proj = (const float*)d_in[4];
    float* out = (float*)d_out;

    cudaFuncSetAttribute(gemm_tf32<0>,
        cudaFuncAttributeMaxDynamicSharedMemorySize, GEMM_SMEM_BYTES);
    cudaFuncSetAttribute(gemm_tf32<1>,
        cudaFuncAttributeMaxDynamicSharedMemorySize, GEMM_SMEM_BYTES);
    cudaFuncSetAttribute(attn_tf32,
        cudaFuncAttributeMaxDynamicSharedMemorySize, ATTN_SMEM_BYTES);

    gemm_tf32<0><<<dim3(3*DIMD/128, MTOT/128), 128, GEMM_SMEM_BYTES>>>(x, w_qkv, b_qkv, nullptr, 3*DIMD);
    attn_tf32<<<dim3(SEQ/128, NH, BATCH), 256, ATTN_SMEM_BYTES>>>();
    gemm_tf32<1><<<dim3(DIMD/128, MTOT/128), 128, GEMM_SMEM_BYTES>>>(nullptr, w_proj, b_proj, out, DIMD);
}

// round 6
// speedup vs baseline: 1.1300x; 1.1300x over previous
#include <cuda_runtime.h>

#define DIMD  1024
#define NH    16
#define DH    64
#define BATCH 4
#define SEQ   2048
#define MTOT  (BATCH*SEQ)   // 8192

// Scratch (allocation-free rule: __device__ globals)
__device__ float g_Q[BATCH*NH*SEQ*DH];   // [B,H,S,Dh]
__device__ float g_K[BATCH*NH*SEQ*DH];
__device__ float g_V[BATCH*NH*SEQ*DH];
__device__ float g_A[MTOT*DIMD];         // attention output, [B,S,D]

__device__ __forceinline__ float f2tf32(float x) {
    unsigned u;
    asm("cvt.rna.tf32.f32 %0, %1;" : "=r"(u) : "f"(x));
    return __uint_as_float(u);
}

__device__ __forceinline__ void mma_tf32(
    float& c0, float& c1, float& c2, float& c3,
    unsigned a0, unsigned a1, unsigned a2, unsigned a3,
    unsigned b0, unsigned b1)
{
    asm volatile(
        "mma.sync.aligned.m16n8k8.row.col.f32.tf32.tf32.f32 "
        "{%0,%1,%2,%3}, {%4,%5,%6,%7}, {%8,%9}, {%0,%1,%2,%3};"
        : "+f"(c0), "+f"(c1), "+f"(c2), "+f"(c3)
        : "r"(a0), "r"(a1), "r"(a2), "r"(a3), "r"(b0), "r"(b1));
}

// ---------------------------------------------------------------------------
// TF32 GEMM: round-2 geometry (block 128x128, 8 warps 4Mx2N, warp 32x64,
// BK=32, As stride 36, Bs stride 136 — conflict-free fragment LDS),
// now DOUBLE-BUFFERED with register-staged prefetch, ONE barrier per chunk.
// ---------------------------------------------------------------------------
#define AS_ST 36
#define BS_ST 136
#define AS_STAGE (128*AS_ST)   // 4608
#define BS_STAGE (32*BS_ST)    // 4352
#define GEMM_SMEM_FLOATS (2*(AS_STAGE+BS_STAGE))   // 17920
#define GEMM_SMEM_BYTES  (GEMM_SMEM_FLOATS*4)      // 71680

template<int MODE>
__global__ __launch_bounds__(256, 2)
void gemm_tf32(const float* __restrict__ A, const float* __restrict__ B,
               const float* __restrict__ bias, float* __restrict__ out, int N)
{
    const int K = DIMD;
    extern __shared__ float smg[];
    float* Asm = smg;                  // [2][128][36]
    float* Bsm = smg + 2*AS_STAGE;     // [2][32][136]

    const int tid  = threadIdx.x;
    const int lane = tid & 31;
    const int warp = tid >> 5;
    const int warp_m = warp & 3;
    const int warp_n = warp >> 2;
    const int qr = lane >> 2;
    const int qc = lane & 3;

    const int rowStart = blockIdx.y * 128;
    const int colStart = blockIdx.x * 128;
    const float* Ap = (MODE == 0) ? A : g_A;

    float acc[2][8][4];
    #pragma unroll
    for (int i = 0; i < 2; i++)
        #pragma unroll
        for (int j = 0; j < 8; j++)
            #pragma unroll
            for (int c = 0; c < 4; c++) acc[i][j][c] = 0.f;

    float4 av[4], bv[4];

    auto ldg_chunk = [&](int k0) {
        #pragma unroll
        for (int i = 0; i < 4; i++) {
            const int q = tid + i*256;
            av[i] = *(const float4*)(Ap + (long)(rowStart + (q>>3))*K + k0 + ((q&7)<<2));
            bv[i] = *(const float4*)(B + (long)(k0 + (q>>5))*N + colStart + ((q&31)<<2));
        }
    };
    auto sts_chunk = [&](int s) {
        float* as0 = Asm + s*AS_STAGE;
        float* bs0 = Bsm + s*BS_STAGE;
        #pragma unroll
        for (int i = 0; i < 4; i++) {
            const int q = tid + i*256;
            float* as = as0 + (q>>3)*AS_ST + ((q&7)<<2);
            as[0]=f2tf32(av[i].x); as[1]=f2tf32(av[i].y);
            as[2]=f2tf32(av[i].z); as[3]=f2tf32(av[i].w);
            float* bs = bs0 + (q>>5)*BS_ST + ((q&31)<<2);
            bs[0]=f2tf32(bv[i].x); bs[1]=f2tf32(bv[i].y);
            bs[2]=f2tf32(bv[i].z); bs[3]=f2tf32(bv[i].w);
        }
    };

    ldg_chunk(0);
    sts_chunk(0);
    __syncthreads();

    const int NITER = K / 32;   // 32
    for (int it = 0; it < NITER; it++) {
        const int cur = it & 1, nxt = cur ^ 1;
        const bool more = (it + 1) < NITER;
        if (more) ldg_chunk((it + 1) << 5);

        const float* as0 = Asm + cur*AS_STAGE;
        const float* bs0 = Bsm + cur*BS_STAGE;
        #pragma unroll
        for (int ks = 0; ks < 4; ks++) {
            const int kb = ks * 8;
            unsigned a[2][4], b[8][2];
            #pragma unroll
            for (int ma = 0; ma < 2; ma++) {
                const int r = warp_m*32 + ma*16 + qr;
                a[ma][0] = __float_as_uint(as0[(r    )*AS_ST + kb + qc    ]);
                a[ma][1] = __float_as_uint(as0[(r + 8)*AS_ST + kb + qc    ]);
                a[ma][2] = __float_as_uint(as0[(r    )*AS_ST + kb + qc + 4]);
                a[ma][3] = __float_as_uint(as0[(r + 8)*AS_ST + kb + qc + 4]);
            }
            #pragma unroll
            for (int nb = 0; nb < 8; nb++) {
                const int cc = warp_n*64 + nb*8 + qr;
                b[nb][0] = __float_as_uint(bs0[(kb + qc    )*BS_ST + cc]);
                b[nb][1] = __float_as_uint(bs0[(kb + qc + 4)*BS_ST + cc]);
            }
            #pragma unroll
            for (int ma = 0; ma < 2; ma++)
                #pragma unroll
                for (int nb = 0; nb < 8; nb++)
                    mma_tf32(acc[ma][nb][0], acc[ma][nb][1],
                             acc[ma][nb][2], acc[ma][nb][3],
                             a[ma][0], a[ma][1], a[ma][2], a[ma][3],
                             b[nb][0], b[nb][1]);
        }

        if (more) {
            sts_chunk(nxt);
            __syncthreads();
        }
    }

    #pragma unroll
    for (int ma = 0; ma < 2; ma++) {
        const int row0 = rowStart + warp_m*32 + ma*16 + qr;
        #pragma unroll
        for (int nb = 0; nb < 8; nb++) {
            const int col = colStart + warp_n*64 + nb*8 + qc*2;
            const float b0 = bias[col], b1 = bias[col + 1];
            float2 v0 = make_float2(acc[ma][nb][0] + b0, acc[ma][nb][1] + b1);
            float2 v1 = make_float2(acc[ma][nb][2] + b0, acc[ma][nb][3] + b1);
            if (MODE == 0) {
                const int part = col >> 10;
                const int dcol = col & 1023;
                const int head = dcol >> 6;
                const int dh   = dcol & 63;
                float* dst = (part == 0) ? g_Q : (part == 1) ? g_K : g_V;
                {
                    const int bb = row0 >> 11, s = row0 & 2047;
                    *(float2*)(dst + (((bb*NH + head)*SEQ + s) << 6) + dh) = v0;
                }
                {
                    const int row1 = row0 + 8;
                    const int bb = row1 >> 11, s = row1 & 2047;
                    *(float2*)(dst + (((bb*NH + head)*SEQ + s) << 6) + dh) = v1;
                }
            } else {
                *(float2*)(out + (long)row0*N + col) = v0;
                *(float2*)(out + (long)(row0 + 8)*N + col) = v1;
            }
        }
    }
}

// ---------------------------------------------------------------------------
// TF32 tensor-core flash attention (exact round-3 version, the 932us one).
// ---------------------------------------------------------------------------
#define QS_OFF 0
#define KS_OFF 8704               // 128*68
#define VT_OFF 13056              // + 64*68
#define PS_OFF 17408              // + 64*68
#define ATTN_SMEM_FLOATS 26112    // + 128*68
#define ATTN_SMEM_BYTES (ATTN_SMEM_FLOATS*4)   // 104448

__global__ __launch_bounds__(256, 2)
void attn_tf32()
{
    extern __shared__ float sm[];
    float* Qs = sm + QS_OFF;   // [128][68]
    float* Ks = sm + KS_OFF;   // [64][68]
    float* Vt = sm + VT_OFF;   // [64][68]  (transposed V)
    float* Ps = sm + PS_OFF;   // [128][68]

    const int tid  = threadIdx.x;
    const int lane = tid & 31;
    const int warp = tid >> 5;
    const int qr = lane >> 2;
    const int qc = lane & 3;

    const int qt = (int)(gridDim.x - 1) - (int)blockIdx.x;
    const int h = blockIdx.y, b = blockIdx.z;
    const int q0 = qt << 7;

    const long hb = (long)(b*NH + h) * SEQ * DH;
    const float* Qg = g_Q + hb;
    const float* Kg = g_K + hb;
    const float* Vg = g_V + hb;

    #pragma unroll
    for (int i = 0; i < 8; i++) {
        const int q = tid + i*256;
        const int r = q >> 4, dq = (q & 15) << 2;
        float4 t = *(const float4*)(Qg + (q0 + r)*DH + dq);
        float4 c;
        c.x = f2tf32(t.x * 0.125f); c.y = f2tf32(t.y * 0.125f);
        c.z = f2tf32(t.z * 0.125f); c.w = f2tf32(t.w * 0.125f);
        *(float4*)(Qs + r*68 + dq) = c;
    }

    float m0 = -1e30f, m1 = -1e30f, l0 = 0.f, l1 = 0.f;
    float o[8][4];
    #pragma unroll
    for (int nb = 0; nb < 8; nb++)
        #pragma unroll
        for (int c = 0; c < 4; c++) o[nb][c] = 0.f;

    const int rowA = warp*16 + qr;
    const int ktiles = 2*qt + 2;

    for (int kt = 0; kt < ktiles; kt++) {
        const int k0 = kt << 6;
        __syncthreads();

        #pragma unroll
        for (int i = 0; i < 4; i++) {
            const int q = tid + i*256;
            const int r = q >> 4, dq = (q & 15) << 2;
            float4 t = *(const float4*)(Kg + (k0 + r)*DH + dq);
            float4 c;
            c.x = f2tf32(t.x); c.y = f2tf32(t.y);
            c.z = f2tf32(t.z); c.w = f2tf32(t.w);
            *(float4*)(Ks + r*68 + dq) = c;
        }
        {
            const int key = tid & 63;
            const int dq0 = (tid >> 6) << 2;
            #pragma unroll
            for (int i = 0; i < 4; i++) {
                const int dq = dq0 + i*16;
                float4 t = *(const float4*)(Vg + (k0 + key)*DH + dq);
                Vt[(dq+0)*68 + key] = f2tf32(t.x);
                Vt[(dq+1)*68 + key] = f2tf32(t.y);
                Vt[(dq+2)*68 + key] = f2tf32(t.z);
                Vt[(dq+3)*68 + key] = f2tf32(t.w);
            }
        }
        __syncthreads();

        float sv[8][4];
        #pragma unroll
        for (int nb = 0; nb < 8; nb++)
            #pragma unroll
            for (int c = 0; c < 4; c++) sv[nb][c] = 0.f;

        #pragma unroll
        for (int ks = 0; ks < 8; ks++) {
            const int kb = ks*8;
            const unsigned a0 = __float_as_uint(Qs[(rowA    )*68 + kb+qc  ]);
            const unsigned a1 = __float_as_uint(Qs[(rowA + 8)*68 + kb+qc  ]);
            const unsigned a2 = __float_as_uint(Qs[(rowA    )*68 + kb+qc+4]);
            const unsigned a3 = __float_as_uint(Qs[(rowA + 8)*68 + kb+qc+4]);
            #pragma unroll
            for (int nb = 0; nb < 8; nb++) {
                const unsigned b0 = __float_as_uint(Ks[(nb*8+qr)*68 + kb+qc  ]);
                const unsigned b1 = __float_as_uint(Ks[(nb*8+qr)*68 + kb+qc+4]);
                mma_tf32(sv[nb][0], sv[nb][1], sv[nb][2], sv[nb][3],
                         a0, a1, a2, a3, b0, b1);
            }
        }

        if (kt >= 2*qt) {
            const int qg0 = q0 + rowA;
            #pragma unroll
            for (int nb = 0; nb < 8; nb++) {
                const int kg = k0 + nb*8 + 2*qc;
                if (kg     > qg0    ) sv[nb][0] = -1e30f;
                if (kg + 1 > qg0    ) sv[nb][1] = -1e30f;
                if (kg     > qg0 + 8) sv[nb][2] = -1e30f;
                if (kg + 1 > qg0 + 8) sv[nb][3] = -1e30f;
            }
        }

        float mx0 = -1e30f, mx1 = -1e30f;
        #pragma unroll
        for (int nb = 0; nb < 8; nb++) {
            mx0 = fmaxf(mx0, fmaxf(sv[nb][0], sv[nb][1]));
            mx1 = fmaxf(mx1, fmaxf(sv[nb][2], sv[nb][3]));
        }
        mx0 = fmaxf(mx0, __shfl_xor_sync(0xffffffffu, mx0, 1));
        mx0 = fmaxf(mx0, __shfl_xor_sync(0xffffffffu, mx0, 2));
        mx1 = fmaxf(mx1, __shfl_xor_sync(0xffffffffu, mx1, 1));
        mx1 = fmaxf(mx1, __shfl_xor_sync(0xffffffffu, mx1, 2));

        const float m0n = fmaxf(m0, mx0);
        const float m1n = fmaxf(m1, mx1);
        const float al0 = __expf(m0 - m0n);
        const float al1 = __expf(m1 - m1n);
        m0 = m0n; m1 = m1n;

        float ps0 = 0.f, ps1 = 0.f;
        #pragma unroll
        for (int nb = 0; nb < 8; nb++) {
            sv[nb][0] = __expf(sv[nb][0] - m0n);
            sv[nb][1] = __expf(sv[nb][1] - m0n);
            sv[nb][2] = __expf(sv[nb][2] - m1n);
            sv[nb][3] = __expf(sv[nb][3] - m1n);
            ps0 += sv[nb][0] + sv[nb][1];
            ps1 += sv[nb][2] + sv[nb][3];
        }
        ps0 += __shfl_xor_sync(0xffffffffu, ps0, 1);
        ps0 += __shfl_xor_sync(0xffffffffu, ps0, 2);
        ps1 += __shfl_xor_sync(0xffffffffu, ps1, 1);
        ps1 += __shfl_xor_sync(0xffffffffu, ps1, 2);
        l0 = l0*al0 + ps0;
        l1 = l1*al1 + ps1;
        #pragma unroll
        for (int nb = 0; nb < 8; nb++) {
            o[nb][0] *= al0; o[nb][1] *= al0;
            o[nb][2] *= al1; o[nb][3] *= al1;
        }

        #pragma unroll
        for (int nb = 0; nb < 8; nb++) {
            const int kc = nb*8 + 2*qc;
            *(float2*)(Ps + (rowA    )*68 + kc) =
                make_float2(f2tf32(sv[nb][0]), f2tf32(sv[nb][1]));
            *(float2*)(Ps + (rowA + 8)*68 + kc) =
                make_float2(f2tf32(sv[nb][2]), f2tf32(sv[nb][3]));
        }
        __syncthreads();

        #pragma unroll
        for (int ks = 0; ks < 8; ks++) {
            const int kb = ks*8;
            const unsigned a0 = __float_as_uint(Ps[(rowA    )*68 + kb+qc  ]);
            const unsigned a1 = __float_as_uint(Ps[(rowA + 8)*68 + kb+qc  ]);
            const unsigned a2 = __float_as_uint(Ps[(rowA    )*68 + kb+qc+4]);
            const unsigned a3 = __float_as_uint(Ps[(rowA + 8)*68 + kb+qc+4]);
            #pragma unroll
            for (int nb = 0; nb < 8; nb++) {
                const unsigned b0 = __float_as_uint(Vt[(nb*8+qr)*68 + kb+qc  ]);
                const unsigned b1 = __float_as_uint(Vt[(nb*8+qr)*68 + kb+qc+4]);
                mma_tf32(o[nb][0], o[nb][1], o[nb][2], o[nb][3],
                         a0, a1, a2, a3, b0, b1);
            }
        }
    }

    const float inv0 = 1.0f / l0;
    const float inv1 = 1.0f / l1;
    const long r0 = (long)(b*SEQ + q0 + rowA);
    #pragma unroll
    for (int nb = 0; nb < 8; nb++) {
        const int col = h*DH + nb*8 + 2*qc;
        *(float2*)(g_A + r0*DIMD + col) =
            make_float2(o[nb][0]*inv0, o[nb][1]*inv0);
        *(float2*)(g_A + (r0 + 8)*DIMD + col) =
            make_float2(o[nb][2]*inv1, o[nb][3]*inv1);
    }
}

// ---------------------------------------------------------------------------
extern "C" void kernel_launch(void* const* d_in, const int* in_sizes, int n_in,
                              void* d_out, int out_size)
{
    const float* x      = (const float*)d_in[0];
    const float* w_qkv  = (const float*)d_in[1];
    const float* b_qkv  = (const float*)d_in[2];
    const float* w_proj = (const float*)d_in[3];
    const float* b_proj = (const float*)d_in[4];
    float* out = (float*)d_out;

    cudaFuncSetAttribute(gemm_tf32<0>,
        cudaFuncAttributeMaxDynamicSharedMemorySize, GEMM_SMEM_BYTES);
    cudaFuncSetAttribute(gemm_tf32<1>,
        cudaFuncAttributeMaxDynamicSharedMemorySize, GEMM_SMEM_BYTES);
    cudaFuncSetAttribute(attn_tf32,
        cudaFuncAttributeMaxDynamicSharedMemorySize, ATTN_SMEM_BYTES);

    gemm_tf32<0><<<dim3(3*DIMD/128, MTOT/128), 256, GEMM_SMEM_BYTES>>>(x, w_qkv, b_qkv, nullptr, 3*DIMD);
    attn_tf32<<<dim3(SEQ/128, NH, BATCH), 256, ATTN_SMEM_BYTES>>>();
    gemm_tf32<1><<<dim3(DIMD/128, MTOT/128), 256, GEMM_SMEM_BYTES>>>(nullptr, w_proj, b_proj, out, DIMD);
}

// round 8
// speedup vs baseline: 1.1689x; 1.0344x over previous
#include <cuda_runtime.h>
#include <cstdint>

#define DIMD  1024
#define NH    16
#define DH    64
#define BATCH 4
#define SEQ   2048
#define MTOT  (BATCH*SEQ)   // 8192

// Scratch (allocation-free rule: __device__ globals)
__device__ float g_Q[BATCH*NH*SEQ*DH];   // [B,H,S,Dh]
__device__ float g_K[BATCH*NH*SEQ*DH];
__device__ float g_V[BATCH*NH*SEQ*DH];
__device__ float g_A[MTOT*DIMD];         // attention output, [B,S,D] (tf32-rounded)
__device__ float g_XR[MTOT*DIMD];        // x, tf32-rounded
__device__ float g_WR[DIMD*3*DIMD];      // w_qkv, tf32-rounded
__device__ float g_WPR[DIMD*DIMD];       // w_proj, tf32-rounded

__device__ __forceinline__ float f2tf32(float x) {
    unsigned u;
    asm("cvt.rna.tf32.f32 %0, %1;" : "=r"(u) : "f"(x));
    return __uint_as_float(u);
}

__device__ __forceinline__ void mma_tf32(
    float& c0, float& c1, float& c2, float& c3,
    unsigned a0, unsigned a1, unsigned a2, unsigned a3,
    unsigned b0, unsigned b1)
{
    asm volatile(
        "mma.sync.aligned.m16n8k8.row.col.f32.tf32.tf32.f32 "
        "{%0,%1,%2,%3}, {%4,%5,%6,%7}, {%8,%9}, {%0,%1,%2,%3};"
        : "+f"(c0), "+f"(c1), "+f"(c2), "+f"(c3)
        : "r"(a0), "r"(a1), "r"(a2), "r"(a3), "r"(b0), "r"(b1));
}

// ---------------------------------------------------------------------------
// One-time tf32 pre-rounding of x / w_qkv / w_proj (float4 grid-stride)
// ---------------------------------------------------------------------------
#define NX4 (MTOT*DIMD/4)        // 2097152
#define NW4 (DIMD*3*DIMD/4)      // 786432
#define NP4 (DIMD*DIMD/4)        // 262144

__global__ __launch_bounds__(256)
void pre_round(const float* __restrict__ x, const float* __restrict__ wq,
               const float* __restrict__ wp)
{
    const int stride = gridDim.x * blockDim.x;
    for (int i = blockIdx.x*blockDim.x + threadIdx.x; i < NX4; i += stride) {
        float4 t = ((const float4*)x)[i];
        t.x = f2tf32(t.x); t.y = f2tf32(t.y); t.z = f2tf32(t.z); t.w = f2tf32(t.w);
        ((float4*)g_XR)[i] = t;
    }
    for (int i = blockIdx.x*blockDim.x + threadIdx.x; i < NW4; i += stride) {
        float4 t = ((const float4*)wq)[i];
        t.x = f2tf32(t.x); t.y = f2tf32(t.y); t.z = f2tf32(t.z); t.w = f2tf32(t.w);
        ((float4*)g_WR)[i] = t;
    }
    for (int i = blockIdx.x*blockDim.x + threadIdx.x; i < NP4; i += stride) {
        float4 t = ((const float4*)wp)[i];
        t.x = f2tf32(t.x); t.y = f2tf32(t.y); t.z = f2tf32(t.z); t.w = f2tf32(t.w);
        ((float4*)g_WPR)[i] = t;
    }
}

// ---------------------------------------------------------------------------
// TF32 GEMM (round-3 geometry: block 128x128, 8 warps 4Mx2N, warp 32x64,
// BK=32, As[128][36], Bs[32][136]). Inputs pre-rounded -> pure vector fills.
// MODE 0: A=g_XR, B=g_WR (N=3072), scatter into g_Q/g_K/g_V
// MODE 1: A=g_A,  B=g_WPR (N=1024), row-major write to out
// ---------------------------------------------------------------------------
template<int MODE>
__global__ __launch_bounds__(256, 2)
void gemm_tf32(const float* __restrict__ bias, float* __restrict__ out, int N)
{
    const int K = DIMD;
    __shared__ float As[128][36];
    __shared__ float Bs[32][136];

    const int tid  = threadIdx.x;
    const int lane = tid & 31;
    const int warp = tid >> 5;
    const int warp_m = warp & 3;
    const int warp_n = warp >> 2;
    const int qr = lane >> 2;
    const int qc = lane & 3;

    const int rowStart = blockIdx.y * 128;
    const int colStart = blockIdx.x * 128;
    const float* Ap = (MODE == 0) ? g_XR : g_A;
    const float* Bp = (MODE == 0) ? g_WR : g_WPR;

    float acc[2][8][4];
    #pragma unroll
    for (int i = 0; i < 2; i++)
        #pragma unroll
        for (int j = 0; j < 8; j++)
            #pragma unroll
            for (int c = 0; c < 4; c++) acc[i][j][c] = 0.f;

    for (int k0 = 0; k0 < K; k0 += 32) {
        float4 av[4], bv[4];
        #pragma unroll
        for (int i = 0; i < 4; i++) {
            const int q = tid + i*256;
            av[i] = *(const float4*)(Ap + (long)(rowStart + (q>>3))*K + k0 + ((q&7)<<2));
            bv[i] = *(const float4*)(Bp + (long)(k0 + (q>>5))*N + colStart + ((q&31)<<2));
        }
        __syncthreads();
        #pragma unroll
        for (int i = 0; i < 4; i++) {
            const int q = tid + i*256;
            *(float4*)(&As[q>>3][(q&7)<<2]) = av[i];
            *(float4*)(&Bs[q>>5][(q&31)<<2]) = bv[i];
        }
        __syncthreads();

        #pragma unroll
        for (int ks = 0; ks < 4; ks++) {
            const int kb = ks * 8;
            unsigned a[2][4], b[8][2];
            #pragma unroll
            for (int ma = 0; ma < 2; ma++) {
                const int r = warp_m*32 + ma*16 + qr;
                a[ma][0] = __float_as_uint(As[r    ][kb + qc    ]);
                a[ma][1] = __float_as_uint(As[r + 8][kb + qc    ]);
                a[ma][2] = __float_as_uint(As[r    ][kb + qc + 4]);
                a[ma][3] = __float_as_uint(As[r + 8][kb + qc + 4]);
            }
            #pragma unroll
            for (int nb = 0; nb < 8; nb++) {
                const int cc = warp_n*64 + nb*8 + qr;
                b[nb][0] = __float_as_uint(Bs[kb + qc    ][cc]);
                b[nb][1] = __float_as_uint(Bs[kb + qc + 4][cc]);
            }
            #pragma unroll
            for (int ma = 0; ma < 2; ma++)
                #pragma unroll
                for (int nb = 0; nb < 8; nb++)
                    mma_tf32(acc[ma][nb][0], acc[ma][nb][1],
                             acc[ma][nb][2], acc[ma][nb][3],
                             a[ma][0], a[ma][1], a[ma][2], a[ma][3],
                             b[nb][0], b[nb][1]);
        }
    }

    #pragma unroll
    for (int ma = 0; ma < 2; ma++) {
        const int row0 = rowStart + warp_m*32 + ma*16 + qr;
        #pragma unroll
        for (int nb = 0; nb < 8; nb++) {
            const int col = colStart + warp_n*64 + nb*8 + qc*2;
            const float b0 = bias[col], b1 = bias[col + 1];
            float2 v0 = make_float2(acc[ma][nb][0] + b0, acc[ma][nb][1] + b1);
            float2 v1 = make_float2(acc[ma][nb][2] + b0, acc[ma][nb][3] + b1);
            if (MODE == 0) {
                const int part = col >> 10;
                const int dcol = col & 1023;
                const int head = dcol >> 6;
                const int dh   = dcol & 63;
                float* dst = (part == 0) ? g_Q : (part == 1) ? g_K : g_V;
                {
                    const int bb = row0 >> 11, s = row0 & 2047;
                    *(float2*)(dst + (((bb*NH + head)*SEQ + s) << 6) + dh) = v0;
                }
                {
                    const int row1 = row0 + 8;
                    const int bb = row1 >> 11, s = row1 & 2047;
                    *(float2*)(dst + (((bb*NH + head)*SEQ + s) << 6) + dh) = v1;
                }
            } else {
                *(float2*)(out + (long)row0*N + col) = v0;
                *(float2*)(out + (long)(row0 + 8)*N + col) = v1;
            }
        }
    }
}

// ---------------------------------------------------------------------------
// TF32 flash attention v2:
//  - double-buffered K/V tiles (LDG at loop top, STS after PV, ONE barrier)
//  - P redistributed via warp shuffles (no Ps SMEM, no mid barrier)
// SMEM: Qs[128][68] + 2x Ks[64][68] + 2x Vt[64][68] = 104448 B, 2 CTA/SM.
// ---------------------------------------------------------------------------
#define KV_STAGE (64*68)          // 4352
#define ATTN_SMEM_FLOATS (128*68 + 4*KV_STAGE)   // 26112
#define ATTN_SMEM_BYTES (ATTN_SMEM_FLOATS*4)     // 104448

__global__ __launch_bounds__(256, 2)
void attn_tf32()
{
    extern __shared__ float sm[];
    float* Qs  = sm;                       // [128][68]
    float* KsB = sm + 8704;                // [2][64][68]
    float* VtB = sm + 8704 + 2*KV_STAGE;   // [2][64][68]

    const int tid  = threadIdx.x;
    const int lane = tid & 31;
    const int warp = tid >> 5;
    const int qr = lane >> 2;
    const int qc = lane & 3;

    const int qt = (int)(gridDim.x - 1) - (int)blockIdx.x;   // heavy tiles first
    const int h = blockIdx.y, b = blockIdx.z;
    const int q0 = qt << 7;

    const long hb = (long)(b*NH + h) * SEQ * DH;
    const float* Qg = g_Q + hb;
    const float* Kg = g_K + hb;
    const float* Vg = g_V + hb;

    // Q tile [128][64], scale 1/8, tf32
    #pragma unroll
    for (int i = 0; i < 8; i++) {
        const int q = tid + i*256;
        const int r = q >> 4, dq = (q & 15) << 2;
        float4 t = *(const float4*)(Qg + (q0 + r)*DH + dq);
        float4 c;
        c.x = f2tf32(t.x * 0.125f); c.y = f2tf32(t.y * 0.125f);
        c.z = f2tf32(t.z * 0.125f); c.w = f2tf32(t.w * 0.125f);
        *(float4*)(Qs + r*68 + dq) = c;
    }

    const int vkey = tid & 63;
    const int vdq0 = (tid >> 6) << 2;

    // prologue: fill K/V buffer 0 (tile 0)
    {
        float* Ks = KsB;
        float* Vt = VtB;
        #pragma unroll
        for (int i = 0; i < 4; i++) {
            const int q = tid + i*256;
            const int r = q >> 4, dq = (q & 15) << 2;
            float4 t = *(const float4*)(Kg + r*DH + dq);
            float* ks = Ks + r*68 + dq;
            ks[0]=f2tf32(t.x); ks[1]=f2tf32(t.y);
            ks[2]=f2tf32(t.z); ks[3]=f2tf32(t.w);
            const int dq2 = vdq0 + i*16;
            float4 v = *(const float4*)(Vg + vkey*DH + dq2);
            Vt[(dq2+0)*68 + vkey] = f2tf32(v.x);
            Vt[(dq2+1)*68 + vkey] = f2tf32(v.y);
            Vt[(dq2+2)*68 + vkey] = f2tf32(v.z);
            Vt[(dq2+3)*68 + vkey] = f2tf32(v.w);
        }
    }
    __syncthreads();

    float m0 = -1e30f, m1 = -1e30f, l0 = 0.f, l1 = 0.f;
    float o[8][4];
    #pragma unroll
    for (int nb = 0; nb < 8; nb++)
        #pragma unroll
        for (int c = 0; c < 4; c++) o[nb][c] = 0.f;

    const int rowA = warp*16 + qr;
    const int ktiles = 2*qt + 2;
    const int srcA = (lane & 28) | (qc >> 1);   // 4*qr + qc/2
    const int srcB = srcA + 2;
    const bool odd = (qc & 1);

    for (int kt = 0; kt < ktiles; kt++) {
        const int cur = kt & 1;
        const bool more = (kt + 1) < ktiles;
        const float* Ks = KsB + cur*KV_STAGE;
        const float* Vt = VtB + cur*KV_STAGE;

        // hoisted loads for tile kt+1 (complete during compute below)
        float4 kreg[4], vreg[4];
        if (more) {
            const int k1 = (kt + 1) << 6;
            #pragma unroll
            for (int i = 0; i < 4; i++) {
                const int q = tid + i*256;
                kreg[i] = *(const float4*)(Kg + (k1 + (q>>4))*DH + ((q&15)<<2));
                vreg[i] = *(const float4*)(Vg + (k1 + vkey)*DH + vdq0 + i*16);
            }
        }

        // S = Q @ K^T
        float sv[8][4];
        #pragma unroll
        for (int nb = 0; nb < 8; nb++)
            #pragma unroll
            for (int c = 0; c < 4; c++) sv[nb][c] = 0.f;

        #pragma unroll
        for (int ks = 0; ks < 8; ks++) {
            const int kb = ks*8;
            const unsigned a0 = __float_as_uint(Qs[(rowA    )*68 + kb+qc  ]);
            const unsigned a1 = __float_as_uint(Qs[(rowA + 8)*68 + kb+qc  ]);
            const unsigned a2 = __float_as_uint(Qs[(rowA    )*68 + kb+qc+4]);
            const unsigned a3 = __float_as_uint(Qs[(rowA + 8)*68 + kb+qc+4]);
            #pragma unroll
            for (int nb = 0; nb < 8; nb++) {
                const unsigned b0 = __float_as_uint(Ks[(nb*8+qr)*68 + kb+qc  ]);
                const unsigned b1 = __float_as_uint(Ks[(nb*8+qr)*68 + kb+qc+4]);
                mma_tf32(sv[nb][0], sv[nb][1], sv[nb][2], sv[nb][3],
                         a0, a1, a2, a3, b0, b1);
            }
        }

        // causal mask (two diagonal k-tiles only)
        if (kt >= 2*qt) {
            const int k0 = kt << 6;
            const int qg0 = q0 + rowA;
            #pragma unroll
            for (int nb = 0; nb < 8; nb++) {
                const int kg = k0 + nb*8 + 2*qc;
                if (kg     > qg0    ) sv[nb][0] = -1e30f;
                if (kg + 1 > qg0    ) sv[nb][1] = -1e30f;
                if (kg     > qg0 + 8) sv[nb][2] = -1e30f;
                if (kg + 1 > qg0 + 8) sv[nb][3] = -1e30f;
            }
        }

        // online softmax (rows rowA, rowA+8; stats across 4 qc lanes)
        float mx0 = -1e30f, mx1 = -1e30f;
        #pragma unroll
        for (int nb = 0; nb < 8; nb++) {
            mx0 = fmaxf(mx0, fmaxf(sv[nb][0], sv[nb][1]));
            mx1 = fmaxf(mx1, fmaxf(sv[nb][2], sv[nb][3]));
        }
        mx0 = fmaxf(mx0, __shfl_xor_sync(0xffffffffu, mx0, 1));
        mx0 = fmaxf(mx0, __shfl_xor_sync(0xffffffffu, mx0, 2));
        mx1 = fmaxf(mx1, __shfl_xor_sync(0xffffffffu, mx1, 1));
        mx1 = fmaxf(mx1, __shfl_xor_sync(0xffffffffu, mx1, 2));

        const float m0n = fmaxf(m0, mx0);
        const float m1n = fmaxf(m1, mx1);
        const float al0 = __expf(m0 - m0n);
        const float al1 = __expf(m1 - m1n);
        m0 = m0n; m1 = m1n;

        float ps0 = 0.f, ps1 = 0.f;
        #pragma unroll
        for (int nb = 0; nb < 8; nb++) {
            sv[nb][0] = __expf(sv[nb][0] - m0n);
            sv[nb][1] = __expf(sv[nb][1] - m0n);
            sv[nb][2] = __expf(sv[nb][2] - m1n);
            sv[nb][3] = __expf(sv[nb][3] - m1n);
            ps0 += sv[nb][0] + sv[nb][1];
            ps1 += sv[nb][2] + sv[nb][3];
        }
        ps0 += __shfl_xor_sync(0xffffffffu, ps0, 1);
        ps0 += __shfl_xor_sync(0xffffffffu, ps0, 2);
        ps1 += __shfl_xor_sync(0xffffffffu, ps1, 1);
        ps1 += __shfl_xor_sync(0xffffffffu, ps1, 2);
        l0 = l0*al0 + ps0;
        l1 = l1*al1 + ps1;
        #pragma unroll
        for (int nb = 0; nb < 8; nb++) {
            o[nb][0] *= al0; o[nb][1] *= al0;
            o[nb][2] *= al1; o[nb][3] *= al1;
            sv[nb][0] = f2tf32(sv[nb][0]);   // round P once, pre-shuffle
            sv[nb][1] = f2tf32(sv[nb][1]);
            sv[nb][2] = f2tf32(sv[nb][2]);
            sv[nb][3] = f2tf32(sv[nb][3]);
        }

        // O += P @ V : P fragments via warp shuffles (no SMEM round-trip)
        #pragma unroll
        for (int ks = 0; ks < 8; ks++) {
            const int kb = ks*8;
            const float p00 = __shfl_sync(0xffffffffu, sv[ks][0], srcA);
            const float p01 = __shfl_sync(0xffffffffu, sv[ks][1], srcA);
            const float p10 = __shfl_sync(0xffffffffu, sv[ks][2], srcA);
            const float p11 = __shfl_sync(0xffffffffu, sv[ks][3], srcA);
            const float r00 = __shfl_sync(0xffffffffu, sv[ks][0], srcB);
            const float r01 = __shfl_sync(0xffffffffu, sv[ks][1], srcB);
            const float r10 = __shfl_sync(0xffffffffu, sv[ks][2], srcB);
            const float r11 = __shfl_sync(0xffffffffu, sv[ks][3], srcB);
            const unsigned a0 = __float_as_uint(odd ? p01 : p00);
            const unsigned a1 = __float_as_uint(odd ? p11 : p10);
            const unsigned a2 = __float_as_uint(odd ? r01 : r00);
            const unsigned a3 = __float_as_uint(odd ? r11 : r10);
            #pragma unroll
            for (int nb = 0; nb < 8; nb++) {
                const unsigned b0 = __float_as_uint(Vt[(nb*8+qr)*68 + kb+qc  ]);
                const unsigned b1 = __float_as_uint(Vt[(nb*8+qr)*68 + kb+qc+4]);
                mma_tf32(o[nb][0], o[nb][1], o[nb][2], o[nb][3],
                         a0, a1, a2, a3, b0, b1);
            }
        }

        // store next tile into the other buffer; single barrier per iteration
        if (more) {
            const int nxt = cur ^ 1;
            float* KsD = KsB + nxt*KV_STAGE;
            float* VtD = VtB + nxt*KV_STAGE;
            #pragma unroll
            for (int i = 0; i < 4; i++) {
                const int q = tid + i*256;
                const int r = q >> 4, dq = (q & 15) << 2;
                float* ks = KsD + r*68 + dq;
                ks[0]=f2tf32(kreg[i].x); ks[1]=f2tf32(kreg[i].y);
                ks[2]=f2tf32(kreg[i].z); ks[3]=f2tf32(kreg[i].w);
                const int dq2 = vdq0 + i*16;
                VtD[(dq2+0)*68 + vkey] = f2tf32(vreg[i].x);
                VtD[(dq2+1)*68 + vkey] = f2tf32(vreg[i].y);
                VtD[(dq2+2)*68 + vkey] = f2tf32(vreg[i].z);
                VtD[(dq2+3)*68 + vkey] = f2tf32(vreg[i].w);
            }
            __syncthreads();
        }
    }

    // normalize + write merged-head [B,S,D], tf32-rounded (feeds proj GEMM)
    const float inv0 = 1.0f / l0;
    const float inv1 = 1.0f / l1;
    const long r0 = (long)(b*SEQ + q0 + rowA);
    #pragma unroll
    for (int nb = 0; nb < 8; nb++) {
        const int col = h*DH + nb*8 + 2*qc;
        *(float2*)(g_A + r0*DIMD + col) =
            make_float2(f2tf32(o[nb][0]*inv0), f2tf32(o[nb][1]*inv0));
        *(float2*)(g_A + (r0 + 8)*DIMD + col) =
            make_float2(f2tf32(o[nb][2]*inv1), f2tf32(o[nb][3]*inv1));
    }
}

// ---------------------------------------------------------------------------
extern "C" void kernel_launch(void* const* d_in, const int* in_sizes, int n_in,
                              void* d_out, int out_size)
{
    const float* x      = (const float*)d_in[0];
    const float* w_qkv  = (const float*)d_in[1];
    const float* b_qkv  = (const float*)d_in[2];
    const float* w_proj = (const float*)d_in[3];
    const float* b_proj = (const float*)d_in[4];
    float* out = (float*)d_out;

    cudaFuncSetAttribute(attn_tf32,
        cudaFuncAttributeMaxDynamicSharedMemorySize, ATTN_SMEM_BYTES);

    pre_round<<<1024, 256>>>(x, w_qkv, w_proj);
    gemm_tf32<0><<<dim3(3*DIMD/128, MTOT/128), 256>>>(b_qkv, nullptr, 3*DIMD);
    attn_tf32<<<dim3(SEQ/128, NH, BATCH), 256, ATTN_SMEM_BYTES>>>();
    gemm_tf32<1><<<dim3(DIMD/128, MTOT/128), 256>>>(b_proj, out, DIMD);
}

// round 9
// speedup vs baseline: 2.1808x; 1.8657x over previous
#include <cuda_runtime.h>
#include <cuda_fp16.h>
#include <cstdint>

#define DIMD  1024
#define NH    16
#define DH    64
#define BATCH 4
#define SEQ   2048
#define MTOT  (BATCH*SEQ)   // 8192

// Scratch (allocation-free rule: __device__ globals)
__device__ __align__(16) __half g_QH[BATCH*NH*SEQ*DH];   // [B,H,S,Dh]
__device__ __align__(16) __half g_KH[BATCH*NH*SEQ*DH];
__device__ __align__(16) __half g_VH[BATCH*NH*SEQ*DH];
__device__ __align__(16) __half g_AH[MTOT*DIMD];         // attn out, [B,S,D]
__device__ __align__(16) __half g_XH[MTOT*DIMD];         // x as fp16
__device__ __align__(16) uint32_t g_WQP[(DIMD/2)*3*DIMD]; // w_qkv packed k-pairs
__device__ __align__(16) uint32_t g_WPP[(DIMD/2)*DIMD];   // w_proj packed

__device__ __forceinline__ unsigned h2u(__half2 h) {
    return *reinterpret_cast<unsigned*>(&h);
}

__device__ __forceinline__ void mma_f16(
    float& c0, float& c1, float& c2, float& c3,
    unsigned a0, unsigned a1, unsigned a2, unsigned a3,
    unsigned b0, unsigned b1)
{
    asm volatile(
        "mma.sync.aligned.m16n8k16.row.col.f32.f16.f16.f32 "
        "{%0,%1,%2,%3}, {%4,%5,%6,%7}, {%8,%9}, {%0,%1,%2,%3};"
        : "+f"(c0), "+f"(c1), "+f"(c2), "+f"(c3)
        : "r"(a0), "r"(a1), "r"(a2), "r"(a3), "r"(b0), "r"(b1));
}

// ---------------------------------------------------------------------------
// One-time prep: x -> fp16; w_qkv / w_proj -> k-pairwise packed half2
// ---------------------------------------------------------------------------
#define NX4 (MTOT*DIMD/4)            // 2097152 float4 units
#define NWQ ((DIMD/2)*(3*DIMD/4))    // 512*768
#define NWP ((DIMD/2)*(DIMD/4))      // 512*256

__global__ __launch_bounds__(256)
void prep(const float* __restrict__ x, const float* __restrict__ wq,
          const float* __restrict__ wp)
{
    const int stride = gridDim.x * blockDim.x;
    for (int i = blockIdx.x*blockDim.x + threadIdx.x; i < NX4; i += stride) {
        float4 t = ((const float4*)x)[i];
        uint2 o;
        o.x = h2u(__floats2half2_rn(t.x, t.y));
        o.y = h2u(__floats2half2_rn(t.z, t.w));
        ((uint2*)g_XH)[i] = o;
    }
    for (int i = blockIdx.x*blockDim.x + threadIdx.x; i < NWQ; i += stride) {
        const int k2 = i / 768, n4 = i % 768;
        const float4 a = *(const float4*)(wq + (long)(2*k2  )*3072 + n4*4);
        const float4 b = *(const float4*)(wq + (long)(2*k2+1)*3072 + n4*4);
        uint4 o;
        o.x = h2u(__floats2half2_rn(a.x, b.x));
        o.y = h2u(__floats2half2_rn(a.y, b.y));
        o.z = h2u(__floats2half2_rn(a.z, b.z));
        o.w = h2u(__floats2half2_rn(a.w, b.w));
        ((uint4*)g_WQP)[i] = o;
    }
    for (int i = blockIdx.x*blockDim.x + threadIdx.x; i < NWP; i += stride) {
        const int k2 = i / 256, n4 = i % 256;
        const float4 a = *(const float4*)(wp + (long)(2*k2  )*1024 + n4*4);
        const float4 b = *(const float4*)(wp + (long)(2*k2+1)*1024 + n4*4);
        uint4 o;
        o.x = h2u(__floats2half2_rn(a.x, b.x));
        o.y = h2u(__floats2half2_rn(a.y, b.y));
        o.z = h2u(__floats2half2_rn(a.z, b.z));
        o.w = h2u(__floats2half2_rn(a.w, b.w));
        ((uint4*)g_WPP)[i] = o;
    }
}

// ---------------------------------------------------------------------------
// FP16 GEMM: block 128x128, 8 warps (4Mx2N), warp 32x64, BK=32 halves.
// As2[128][20] uint32 (k-pairs), Bs2[16][136] uint32. m16n8k16 mma.
// MODE 0: A=g_XH, B=g_WQP (N=3072), scatter half into g_QH/g_KH/g_VH
// MODE 1: A=g_AH, B=g_WPP (N=1024), fp32 row-major write to out
// ---------------------------------------------------------------------------
#define GA_ST 20
#define GB_ST 136

template<int MODE>
__global__ __launch_bounds__(256, 2)
void gemm_f16(const float* __restrict__ bias, float* __restrict__ out, int N)
{
    __shared__ uint32_t As2[128][GA_ST];
    __shared__ uint32_t Bs2[16][GB_ST];

    const int tid  = threadIdx.x;
    const int lane = tid & 31;
    const int warp = tid >> 5;
    const int warp_m = warp & 3;
    const int warp_n = warp >> 2;
    const int qr = lane >> 2;
    const int qc = lane & 3;

    const int rowStart = blockIdx.y * 128;
    const int colStart = blockIdx.x * 128;
    const __half* Ap = (MODE == 0) ? g_XH : g_AH;
    const uint32_t* Bp = (MODE == 0) ? g_WQP : g_WPP;

    float acc[2][8][4];
    #pragma unroll
    for (int i = 0; i < 2; i++)
        #pragma unroll
        for (int j = 0; j < 8; j++)
            #pragma unroll
            for (int c = 0; c < 4; c++) acc[i][j][c] = 0.f;

    for (int k0 = 0; k0 < DIMD; k0 += 32) {
        uint4 av[2], bv[2];
        #pragma unroll
        for (int i = 0; i < 2; i++) {
            const int q = tid + i*256;
            // A: 128 rows x 4 quads (quad = 8 halves)
            av[i] = *(const uint4*)(Ap + (long)(rowStart + (q>>2))*DIMD + k0 + ((q&3)<<3));
            // B packed: 16 k2-rows x 32 n-quads (quad = 4 uint32)
            bv[i] = *(const uint4*)(Bp + (long)((k0>>1) + (q>>5))*N + colStart + ((q&31)<<2));
        }
        __syncthreads();
        #pragma unroll
        for (int i = 0; i < 2; i++) {
            const int q = tid + i*256;
            *(uint4*)(&As2[q>>2][(q&3)<<2]) = av[i];
            *(uint4*)(&Bs2[q>>5][(q&31)<<2]) = bv[i];
        }
        __syncthreads();

        #pragma unroll
        for (int ks = 0; ks < 2; ks++) {
            const int kb2 = ks * 8;
            unsigned a[2][4], b[8][2];
            #pragma unroll
            for (int ma = 0; ma < 2; ma++) {
                const int r = warp_m*32 + ma*16 + qr;
                a[ma][0] = As2[r    ][kb2 + qc    ];
                a[ma][1] = As2[r + 8][kb2 + qc    ];
                a[ma][2] = As2[r    ][kb2 + qc + 4];
                a[ma][3] = As2[r + 8][kb2 + qc + 4];
            }
            #pragma unroll
            for (int nb = 0; nb < 8; nb++) {
                const int cc = warp_n*64 + nb*8 + qr;
                b[nb][0] = Bs2[kb2 + qc    ][cc];
                b[nb][1] = Bs2[kb2 + qc + 4][cc];
            }
            #pragma unroll
            for (int ma = 0; ma < 2; ma++)
                #pragma unroll
                for (int nb = 0; nb < 8; nb++)
                    mma_f16(acc[ma][nb][0], acc[ma][nb][1],
                            acc[ma][nb][2], acc[ma][nb][3],
                            a[ma][0], a[ma][1], a[ma][2], a[ma][3],
                            b[nb][0], b[nb][1]);
        }
    }

    #pragma unroll
    for (int ma = 0; ma < 2; ma++) {
        const int row0 = rowStart + warp_m*32 + ma*16 + qr;
        #pragma unroll
        for (int nb = 0; nb < 8; nb++) {
            const int col = colStart + warp_n*64 + nb*8 + qc*2;
            const float b0 = bias[col], b1 = bias[col + 1];
            const float v00 = acc[ma][nb][0] + b0, v01 = acc[ma][nb][1] + b1;
            const float v10 = acc[ma][nb][2] + b0, v11 = acc[ma][nb][3] + b1;
            if (MODE == 0) {
                const int part = col >> 10;
                const int dcol = col & 1023;
                const int head = dcol >> 6;
                const int dh   = dcol & 63;
                __half* dst = (part == 0) ? g_QH : (part == 1) ? g_KH : g_VH;
                {
                    const int bb = row0 >> 11, s = row0 & 2047;
                    *(__half2*)(dst + (((bb*NH + head)*SEQ + s) << 6) + dh) =
                        __floats2half2_rn(v00, v01);
                }
                {
                    const int row1 = row0 + 8;
                    const int bb = row1 >> 11, s = row1 & 2047;
                    *(__half2*)(dst + (((bb*NH + head)*SEQ + s) << 6) + dh) =
                        __floats2half2_rn(v10, v11);
                }
            } else {
                *(float2*)(out + (long)row0*N + col) = make_float2(v00, v01);
                *(float2*)(out + (long)(row0 + 8)*N + col) = make_float2(v10, v11);
            }
        }
    }
}

// ---------------------------------------------------------------------------
// FP16 flash attention:
//  - m16n8k16 mma for QK and PV
//  - P stays in registers (C-frag of S == A-frag of PV for fp16 k16)
//  - double-buffered K/V, hoisted LDG, ONE barrier per k-tile
// SMEM (uint32 words): Qs2[128][36] + 2x Ks2[64][36] + 2x Vt2[64][36]
// ---------------------------------------------------------------------------
#define AQ_ST 36
#define KV_STAGE (64*AQ_ST)                       // 2304 words
#define ATTN_SMEM_WORDS (128*AQ_ST + 4*KV_STAGE)  // 13824
#define ATTN_SMEM_BYTES (ATTN_SMEM_WORDS*4)       // 55296

__global__ __launch_bounds__(256, 2)
void attn_f16()
{
    extern __shared__ uint32_t smw[];
    uint32_t* Qs2 = smw;                         // [128][36]
    uint32_t* KsB = smw + 128*AQ_ST;             // [2][64][36]
    uint32_t* VtB = smw + 128*AQ_ST + 2*KV_STAGE;// [2][64][36]  (V^T, key-pairs)

    const int tid  = threadIdx.x;
    const int lane = tid & 31;
    const int warp = tid >> 5;
    const int qr = lane >> 2;
    const int qc = lane & 3;

    const int qt = (int)(gridDim.x - 1) - (int)blockIdx.x;   // heavy tiles first
    const int h = blockIdx.y, b = blockIdx.z;
    const int q0 = qt << 7;

    const long hb = (long)(b*NH + h) * SEQ * DH;
    const __half* Qg = g_QH + hb;
    const __half* Kg = g_KH + hb;
    const __half* Vg = g_VH + hb;

    // Q tile [128][64h], scale by 1/8 (exact in fp16)
    const __half2 hscale = __float2half2_rn(0.125f);
    #pragma unroll
    for (int i = 0; i < 4; i++) {
        const int q = tid + i*256;               // 1024 quads (8 halves each)
        const int r = q >> 3, w = q & 7;
        uint4 t = *(const uint4*)(Qg + (q0 + r)*DH + w*8);
        __half2* hp = (__half2*)&t;
        hp[0] = __hmul2(hp[0], hscale); hp[1] = __hmul2(hp[1], hscale);
        hp[2] = __hmul2(hp[2], hscale); hp[3] = __hmul2(hp[3], hscale);
        *(uint4*)(&Qs2[r*AQ_ST + w*4]) = t;
    }

    const int vk2  = tid & 31;                   // key-pair index
    const int vdb  = (tid >> 5) << 3;            // d base (8 per warp)

    // prologue: K/V tile 0 into buffer 0
    {
        #pragma unroll
        for (int i = 0; i < 2; i++) {
            const int q = tid + i*256;           // 512 quads
            const int r = q >> 3, w = q & 7;
            *(uint4*)(&KsB[r*AQ_ST + w*4]) = *(const uint4*)(Kg + r*DH + w*8);
        }
        uint4 lo = *(const uint4*)(Vg + (2*vk2    )*DH + vdb);
        uint4 hi = *(const uint4*)(Vg + (2*vk2 + 1)*DH + vdb);
        const __half* la = (const __half*)&lo;
        const __half* hb2 = (const __half*)&hi;
        #pragma unroll
        for (int j = 0; j < 8; j++)
            VtB[(vdb + j)*AQ_ST + vk2] = h2u(__halves2half2(la[j], hb2[j]));
    }
    __syncthreads();

    float m0 = -1e30f, m1 = -1e30f, l0 = 0.f, l1 = 0.f;
    float o[8][4];
    #pragma unroll
    for (int nb = 0; nb < 8; nb++)
        #pragma unroll
        for (int c = 0; c < 4; c++) o[nb][c] = 0.f;

    const int rowA = warp*16 + qr;
    const int ktiles = 2*qt + 2;

    for (int kt = 0; kt < ktiles; kt++) {
        const int cur = kt & 1;
        const bool more = (kt + 1) < ktiles;
        const uint32_t* Ks = KsB + cur*KV_STAGE;
        const uint32_t* Vt = VtB + cur*KV_STAGE;

        // hoisted loads for tile kt+1
        uint4 kreg[2], vlo, vhi;
        if (more) {
            const int k1 = (kt + 1) << 6;
            #pragma unroll
            for (int i = 0; i < 2; i++) {
                const int q = tid + i*256;
                kreg[i] = *(const uint4*)(Kg + (k1 + (q>>3))*DH + (q&7)*8);
            }
            vlo = *(const uint4*)(Vg + (k1 + 2*vk2    )*DH + vdb);
            vhi = *(const uint4*)(Vg + (k1 + 2*vk2 + 1)*DH + vdb);
        }

        // S = Q @ K^T  (4 k16-steps over d=64)
        float sv[8][4];
        #pragma unroll
        for (int nb = 0; nb < 8; nb++)
            #pragma unroll
            for (int c = 0; c < 4; c++) sv[nb][c] = 0.f;

        #pragma unroll
        for (int ks = 0; ks < 4; ks++) {
            const int kb2 = ks*8;
            const unsigned a0 = Qs2[(rowA    )*AQ_ST + kb2 + qc    ];
            const unsigned a1 = Qs2[(rowA + 8)*AQ_ST + kb2 + qc    ];
            const unsigned a2 = Qs2[(rowA    )*AQ_ST + kb2 + qc + 4];
            const unsigned a3 = Qs2[(rowA + 8)*AQ_ST + kb2 + qc + 4];
            #pragma unroll
            for (int nb = 0; nb < 8; nb++) {
                const unsigned b0 = Ks[(nb*8+qr)*AQ_ST + kb2 + qc    ];
                const unsigned b1 = Ks[(nb*8+qr)*AQ_ST + kb2 + qc + 4];
                mma_f16(sv[nb][0], sv[nb][1], sv[nb][2], sv[nb][3],
                        a0, a1, a2, a3, b0, b1);
            }
        }

        // causal mask (two diagonal k-tiles only)
        if (kt >= 2*qt) {
            const int k0 = kt << 6;
            const int qg0 = q0 + rowA;
            #pragma unroll
            for (int nb = 0; nb < 8; nb++) {
                const int kg = k0 + nb*8 + 2*qc;
                if (kg     > qg0    ) sv[nb][0] = -1e30f;
                if (kg + 1 > qg0    ) sv[nb][1] = -1e30f;
                if (kg     > qg0 + 8) sv[nb][2] = -1e30f;
                if (kg + 1 > qg0 + 8) sv[nb][3] = -1e30f;
            }
        }

        // online softmax
        float mx0 = -1e30f, mx1 = -1e30f;
        #pragma unroll
        for (int nb = 0; nb < 8; nb++) {
            mx0 = fmaxf(mx0, fmaxf(sv[nb][0], sv[nb][1]));
            mx1 = fmaxf(mx1, fmaxf(sv[nb][2], sv[nb][3]));
        }
        mx0 = fmaxf(mx0, __shfl_xor_sync(0xffffffffu, mx0, 1));
        mx0 = fmaxf(mx0, __shfl_xor_sync(0xffffffffu, mx0, 2));
        mx1 = fmaxf(mx1, __shfl_xor_sync(0xffffffffu, mx1, 1));
        mx1 = fmaxf(mx1, __shfl_xor_sync(0xffffffffu, mx1, 2));

        const float m0n = fmaxf(m0, mx0);
        const float m1n = fmaxf(m1, mx1);
        const float al0 = __expf(m0 - m0n);
        const float al1 = __expf(m1 - m1n);
        m0 = m0n; m1 = m1n;

        float ps0 = 0.f, ps1 = 0.f;
        #pragma unroll
        for (int nb = 0; nb < 8; nb++) {
            sv[nb][0] = __expf(sv[nb][0] - m0n);
            sv[nb][1] = __expf(sv[nb][1] - m0n);
            sv[nb][2] = __expf(sv[nb][2] - m1n);
            sv[nb][3] = __expf(sv[nb][3] - m1n);
            ps0 += sv[nb][0] + sv[nb][1];
            ps1 += sv[nb][2] + sv[nb][3];
        }
        ps0 += __shfl_xor_sync(0xffffffffu, ps0, 1);
        ps0 += __shfl_xor_sync(0xffffffffu, ps0, 2);
        ps1 += __shfl_xor_sync(0xffffffffu, ps1, 1);
        ps1 += __shfl_xor_sync(0xffffffffu, ps1, 2);
        l0 = l0*al0 + ps0;
        l1 = l1*al1 + ps1;
        #pragma unroll
        for (int nb = 0; nb < 8; nb++) {
            o[nb][0] *= al0; o[nb][1] *= al0;
            o[nb][2] *= al1; o[nb][3] *= al1;
        }

        // O += P @ V : P fragments are LOCAL (C-frag == A-frag for fp16 k16)
        #pragma unroll
        for (int ks = 0; ks < 4; ks++) {
            const unsigned a0 = h2u(__floats2half2_rn(sv[2*ks  ][0], sv[2*ks  ][1]));
            const unsigned a1 = h2u(__floats2half2_rn(sv[2*ks  ][2], sv[2*ks  ][3]));
            const unsigned a2 = h2u(__floats2half2_rn(sv[2*ks+1][0], sv[2*ks+1][1]));
            const unsigned a3 = h2u(__floats2half2_rn(sv[2*ks+1][2], sv[2*ks+1][3]));
            #pragma unroll
            for (int nb = 0; nb < 8; nb++) {
                const unsigned b0 = Vt[(nb*8+qr)*AQ_ST + ks*8 + qc    ];
                const unsigned b1 = Vt[(nb*8+qr)*AQ_ST + ks*8 + qc + 4];
                mma_f16(o[nb][0], o[nb][1], o[nb][2], o[nb][3],
                        a0, a1, a2, a3, b0, b1);
            }
        }

        // stage next K/V tile; single barrier
        if (more) {
            const int nxt = cur ^ 1;
            uint32_t* KsD = KsB + nxt*KV_STAGE;
            uint32_t* VtD = VtB + nxt*KV_STAGE;
            #pragma unroll
            for (int i = 0; i < 2; i++) {
                const int q = tid + i*256;
                *(uint4*)(&KsD[(q>>3)*AQ_ST + (q&7)*4]) = kreg[i];
            }
            const __half* la = (const __half*)&vlo;
            const __half* hb2 = (const __half*)&vhi;
            #pragma unroll
            for (int j = 0; j < 8; j++)
                VtD[(vdb + j)*AQ_ST + vk2] = h2u(__halves2half2(la[j], hb2[j]));
            __syncthreads();
        }
    }

    // normalize + write merged-head [B,S,D] as fp16 (feeds proj GEMM)
    const float inv0 = 1.0f / l0;
    const float inv1 = 1.0f / l1;
    const long r0 = (long)(b*SEQ + q0 + rowA);
    #pragma unroll
    for (int nb = 0; nb < 8; nb++) {
        const int col = h*DH + nb*8 + 2*qc;
        *(__half2*)(g_AH + r0*DIMD + col) =
            __floats2half2_rn(o[nb][0]*inv0, o[nb][1]*inv0);
        *(__half2*)(g_AH + (r0 + 8)*DIMD + col) =
            __floats2half2_rn(o[nb][2]*inv1, o[nb][3]*inv1);
    }
}

// ---------------------------------------------------------------------------
extern "C" void kernel_launch(void* const* d_in, const int* in_sizes, int n_in,
                              void* d_out, int out_size)
{
    const float* x      = (const float*)d_in[0];
    const float* w_qkv  = (const float*)d_in[1];
    const float* b_qkv  = (const float*)d_in[2];
    const float* w_proj = (const float*)d_in[3];
    const float* b_proj = (const float*)d_in[4];
    float* out = (float*)d_out;

    cudaFuncSetAttribute(attn_f16,
        cudaFuncAttributeMaxDynamicSharedMemorySize, ATTN_SMEM_BYTES);

    prep<<<1024, 256>>>(x, w_qkv, w_proj);
    gemm_f16<0><<<dim3(3*DIMD/128, MTOT/128), 256>>>(b_qkv, nullptr, 3*DIMD);
    attn_f16<<<dim3(SEQ/128, NH, BATCH), 256, ATTN_SMEM_BYTES>>>();
    gemm_f16<1><<<dim3(DIMD/128, MTOT/128), 256>>>(b_proj, out, DIMD);
}